// round 16
// baseline (speedup 1.0000x reference)
#include <cuda_runtime.h>
#include <cuda_fp16.h>
#include <cstdint>

// ---------------------------------------------------------------------------
// S = q @ k^T  [8192,8192];  G = gelu_exact(S/||S||_row*sqrt(8192));
// out = G @ v  [8192,1024].
// fp16 m16n8k16 mma.sync with FP16 ACCUMULATE (rt=8, ~2x the fp32-acc rate),
// promoted to fp32 master accumulators every 2 MMAs (K=32 fp16 chunks --
// random-walk error ~5e-4, inside the measured budget).
// SLDH=80 conflict-free layout. GEMM1 -> fp16 S (P2 cols) + fused sumsq;
// row scales precomputed; in-place fp16 norm+gelu; GEMM2 split-K x4 fp16
// partials; v-transpose overlapped on side stream.
// ---------------------------------------------------------------------------

static __device__ __half g_Gh [8192ull * 8192ull];    // 128 MB S/G fp16 (P2 cols)
static __device__ __half g_VTh[1024ull * 8192ull];    // 16 MB  v^T fp16 (P2 k)
static __device__ __half g_QTh[8192ull * 1024ull];    // 16 MB  q fp16 (P2 k)
static __device__ __half g_KTh[8192ull * 1024ull];    // 16 MB  k fp16 (P2 k)
static __device__ __half g_P  [4ull * 8192ull * 1024ull]; // 64 MB split-K fp16 partials
static __device__ float  g_SQ [8192ull * 128ull];     // 4 MB sumsq partials
static __device__ float  g_RS [8192ull];              // row scales

__device__ __forceinline__ void cp16(uint32_t dst_s, const void* src) {
    asm volatile("cp.async.cg.shared.global [%0], [%1], 16;\n" :: "r"(dst_s), "l"(src));
}

__device__ __forceinline__ uint2 lds64(uint32_t addr) {
    uint2 r;
    asm volatile("ld.shared.v2.b32 {%0, %1}, [%2];" : "=r"(r.x), "=r"(r.y) : "r"(addr));
    return r;
}

// =========================== unified fp16 GEMM =============================
constexpr int BM = 256, BN = 128;
constexpr int BKH  = 64;                 // halves per k-iter
constexpr int SLDH = 80;                 // pair-stride 20 ≡ 4 (mod 16): conflict-free
constexpr int STAGES = 3;
constexpr int TILEAH = BM * SLDH;
constexpr int TILEBH = BN * SLDH;
constexpr int STAGEH = TILEAH + TILEBH;
constexpr unsigned SMEMH_BYTES = STAGES * STAGEH * 2;  // 184320 B
constexpr int ROWB = 32 * SLDH * 2;
constexpr int MTB  = 16 * SLDH * 2;
constexpr int NTB  = 8 * SLDH * 2;

// fp16-accumulate mma: D(f16x2 pair) += A*B, chained via C=D.
__device__ __forceinline__ void mma_f16acc(uint32_t& d0, uint32_t& d1,
                                           uint2 a, uint2 a8, uint2 b) {
    asm volatile(
        "mma.sync.aligned.m16n8k16.row.col.f16.f16.f16.f16 "
        "{%0,%1}, {%2,%3,%4,%5}, {%6,%7}, {%0,%1};\n"
        : "+r"(d0), "+r"(d1)
        : "r"(a.x), "r"(a8.x), "r"(a.y), "r"(a8.y), "r"(b.x), "r"(b.y));
}

struct FragH {
    uint2 a[4];
    uint2 a8[4];
    uint2 b[8];
};

// G1PHASE: fp16 epilogue in P2 layout + fused sumsq. Else fp16 split-K partials.
template <bool G1PHASE>
__global__ __launch_bounds__(256, 1) void gemm_fp16(
    const __half* __restrict__ A, const __half* __restrict__ B, __half* __restrict__ Ch,
    float* __restrict__ sqpart,
    int M, int N, int kcount, int strideA, int strideB)
{
    extern __shared__ __half smh[];
    const uint32_t smem_s = (uint32_t)__cvta_generic_to_shared(smh);

    const int tid  = threadIdx.x;
    const int lane = tid & 31;
    const int wid  = tid >> 5;
    const int wm   = wid & 3;
    const int wn   = wid >> 2;
    const long bm = (long)blockIdx.y * BM;
    const long bn = (long)blockIdx.x * BN;
    const int kbase = blockIdx.z * kcount;
    if (!G1PHASE) Ch += (size_t)blockIdx.z * M * (size_t)N;

    float acc[4][8][4];
#pragma unroll
    for (int i = 0; i < 4; i++)
#pragma unroll
        for (int j = 0; j < 8; j++)
#pragma unroll
            for (int c = 0; c < 4; c++) acc[i][j][c] = 0.f;

    const int nk = kcount / BKH;

    // ---- staging ----
    const int rowA = tid >> 3;
    const int colh = (tid & 7) * 8;
    const __half* aG = A + (size_t)(bm + rowA) * strideA + kbase + colh;
    const __half* bG = B + (size_t)(bn + rowA) * strideB + kbase + colh;
    const uint32_t dA0 = (uint32_t)(rowA * SLDH + colh) * 2u;
    const uint32_t dB0 = (uint32_t)(TILEAH * 2) + dA0;

    auto load_stage = [&](int s, int kt) {
        const uint32_t sb = smem_s + (uint32_t)s * (STAGEH * 2);
        const __half* ak = aG + kt * BKH;
        const __half* bk = bG + kt * BKH;
#pragma unroll
        for (int i = 0; i < 8; i++)
            cp16(sb + dA0 + i * ROWB, ak + (size_t)i * 32 * strideA);
#pragma unroll
        for (int i = 0; i < 4; i++)
            cp16(sb + dB0 + i * ROWB, bk + (size_t)i * 32 * strideB);
        asm volatile("cp.async.commit_group;\n");
    };

#pragma unroll
    for (int s = 0; s < STAGES - 1; s++) load_stage(s, s);

    // ---- fragment base offsets ----
    const int t    = lane & 3;
    const int qrow = lane >> 2;
    const uint32_t aW0 = (uint32_t)((wm * 64 + qrow) * SLDH + 4 * t) * 2u;
    const uint32_t bW0 = (uint32_t)(TILEAH * 2) +
                         (uint32_t)((wn * 64 + qrow) * SLDH + 4 * t) * 2u;

    FragH f0, f1;

    auto load_frags = [&](uint32_t aW, uint32_t bW, FragH& F) {
#pragma unroll
        for (int mt = 0; mt < 4; mt++) {
            F.a[mt]  = lds64(aW + mt * MTB);
            F.a8[mt] = lds64(aW + mt * MTB + NTB);
        }
#pragma unroll
        for (int nt = 0; nt < 8; nt++)
            F.b[nt] = lds64(bW + nt * NTB);
    };

    // 2-chain fp16-acc + promote to fp32 masters
    auto mma_pair = [&]() {
#pragma unroll
        for (int nt = 0; nt < 8; nt++)
#pragma unroll
            for (int mt = 0; mt < 4; mt++) {
                uint32_t d0 = 0u, d1 = 0u;
                mma_f16acc(d0, d1, f0.a[mt], f0.a8[mt], f0.b[nt]);
                mma_f16acc(d0, d1, f1.a[mt], f1.a8[mt], f1.b[nt]);
                float2 p0 = __half22float2(*reinterpret_cast<__half2*>(&d0));
                float2 p1 = __half22float2(*reinterpret_cast<__half2*>(&d1));
                acc[mt][nt][0] += p0.x;
                acc[mt][nt][1] += p0.y;
                acc[mt][nt][2] += p1.x;
                acc[mt][nt][3] += p1.y;
            }
    };

    for (int kt = 0; kt < nk; kt++) {
        asm volatile("cp.async.wait_group %0;\n" :: "n"(STAGES - 2));
        __syncthreads();

        if (kt + STAGES - 1 < nk) {
            load_stage((kt + STAGES - 1) % STAGES, kt + STAGES - 1);
        } else {
            asm volatile("cp.async.commit_group;\n");
        }

        const uint32_t sb = smem_s + (uint32_t)(kt % STAGES) * (STAGEH * 2);
        const uint32_t aW = sb + aW0;
        const uint32_t bW = sb + bW0;

#pragma unroll
        for (int gp = 0; gp < 2; gp++) {           // pairs of 16-k groups
            load_frags(aW + (2 * gp) * 32,     bW + (2 * gp) * 32,     f0);
            load_frags(aW + (2 * gp + 1) * 32, bW + (2 * gp + 1) * 32, f1);
            mma_pair();
        }
    }

    if (G1PHASE) {
        // fused per-row sumsq partials (fp32 masters, pre-rounding)
        const int pidx = blockIdx.x * 2 + wn;
#pragma unroll
        for (int mt = 0; mt < 4; mt++) {
            float s0 = 0.f, s1 = 0.f;
#pragma unroll
            for (int nt = 0; nt < 8; nt++) {
                s0 += acc[mt][nt][0] * acc[mt][nt][0] + acc[mt][nt][1] * acc[mt][nt][1];
                s1 += acc[mt][nt][2] * acc[mt][nt][2] + acc[mt][nt][3] * acc[mt][nt][3];
            }
            s0 += __shfl_xor_sync(0xffffffffu, s0, 1);
            s0 += __shfl_xor_sync(0xffffffffu, s0, 2);
            s1 += __shfl_xor_sync(0xffffffffu, s1, 1);
            s1 += __shfl_xor_sync(0xffffffffu, s1, 2);
            if (t == 0) {
                long r = bm + wm * 64 + mt * 16 + qrow;
                sqpart[(size_t)r * 128 + pidx]       = s0;
                sqpart[(size_t)(r + 8) * 128 + pidx] = s1;
            }
        }
        // fp16 epilogue, P2 layout: one half2 store per pair.
#pragma unroll
        for (int mt = 0; mt < 4; mt++) {
            long r0 = bm + wm * 64 + mt * 16 + qrow;
#pragma unroll
            for (int nt = 0; nt < 8; nt++) {
                long c0 = bn + wn * 64 + (nt >> 1) * 16 + 4 * t + 2 * (nt & 1);
                *reinterpret_cast<__half2*>(&Ch[(size_t)r0 * N + c0]) =
                    __floats2half2_rn(acc[mt][nt][0], acc[mt][nt][1]);
                *reinterpret_cast<__half2*>(&Ch[(size_t)(r0 + 8) * N + c0]) =
                    __floats2half2_rn(acc[mt][nt][2], acc[mt][nt][3]);
            }
        }
    } else {
        // fp16 split-K partials, natural layout
#pragma unroll
        for (int mt = 0; mt < 4; mt++) {
            long r0 = bm + wm * 64 + mt * 16 + qrow;
#pragma unroll
            for (int nt = 0; nt < 8; nt++) {
                long c0 = bn + wn * 64 + nt * 8 + 2 * t;
                *reinterpret_cast<__half2*>(&Ch[(size_t)r0 * N + c0]) =
                    __floats2half2_rn(acc[mt][nt][0], acc[mt][nt][1]);
                *reinterpret_cast<__half2*>(&Ch[(size_t)(r0 + 8) * N + c0]) =
                    __floats2half2_rn(acc[mt][nt][2], acc[mt][nt][3]);
            }
        }
    }
}

// ======================= staging / elementwise kernels =====================
__device__ __constant__ int c_invM[16] = {0,1,8,9,2,3,10,11,4,5,12,13,6,7,14,15};

__global__ __launch_bounds__(256) void stage_h2_kernel(
    const float4* __restrict__ q, __half* __restrict__ qo,
    const float4* __restrict__ k, __half* __restrict__ ko, int ngroups)
{
    const float4* in  = blockIdx.y ? k  : q;
    __half*       out = blockIdx.y ? ko : qo;
    int g = blockIdx.x * 256 + threadIdx.x;
    if (g >= ngroups) return;
    float x[16];
    float4 v0 = in[4 * g], v1 = in[4 * g + 1], v2 = in[4 * g + 2], v3 = in[4 * g + 3];
    x[0]=v0.x; x[1]=v0.y; x[2]=v0.z; x[3]=v0.w;
    x[4]=v1.x; x[5]=v1.y; x[6]=v1.z; x[7]=v1.w;
    x[8]=v2.x; x[9]=v2.y; x[10]=v2.z; x[11]=v2.w;
    x[12]=v3.x; x[13]=v3.y; x[14]=v3.z; x[15]=v3.w;
    uint32_t u[8];
#pragma unroll
    for (int j = 0; j < 8; j++) {
        __half2 h2 = __floats2half2_rn(x[c_invM[2 * j]], x[c_invM[2 * j + 1]]);
        u[j] = *reinterpret_cast<uint32_t*>(&h2);
    }
    uint4* dst = reinterpret_cast<uint4*>(out + (size_t)g * 16);
    dst[0] = make_uint4(u[0], u[1], u[2], u[3]);
    dst[1] = make_uint4(u[4], u[5], u[6], u[7]);
}

// row scales from sumsq partials: one warp per row.
__global__ __launch_bounds__(256) void row_scale_kernel(
    const float* __restrict__ sqpart, float* __restrict__ scales, int N)
{
    int row  = blockIdx.x * 8 + (threadIdx.x >> 5);
    int lane = threadIdx.x & 31;
    const float* p = sqpart + (size_t)row * 128;
    float s = p[lane] + p[lane + 32] + p[lane + 64] + p[lane + 96];
#pragma unroll
    for (int o = 16; o > 0; o >>= 1) s += __shfl_xor_sync(0xffffffffu, s, o);
    if (lane == 0) scales[row] = sqrtf((float)N / s);
}

// IN-PLACE fp16 norm+gelu using precomputed row scale.
__global__ __launch_bounds__(256) void norm_gelu_inplace_kernel(
    __half* __restrict__ Sh, const float* __restrict__ scales, int N)
{
    const int row = blockIdx.x;
    const float scale = scales[row];
    const float inv_sqrt2 = 0.70710678118654752440f;

    uint4* prow = reinterpret_cast<uint4*>(Sh + (size_t)row * N);
    const int n8 = N >> 3;
    for (int i = threadIdx.x; i < n8; i += 256) {
        uint4 u = prow[i];
        uint32_t w[4] = {u.x, u.y, u.z, u.w};
#pragma unroll
        for (int j = 0; j < 4; j++) {
            __half2 h2 = *reinterpret_cast<__half2*>(&w[j]);
            float2 xy = __half22float2(h2);
            float a = xy.x * scale, b = xy.y * scale;
            a = 0.5f * a * (1.f + erff(a * inv_sqrt2));
            b = 0.5f * b * (1.f + erff(b * inv_sqrt2));
            __half2 r = __floats2half2_rn(a, b);
            w[j] = *reinterpret_cast<uint32_t*>(&r);
        }
        prow[i] = make_uint4(w[0], w[1], w[2], w[3]);
    }
}

__global__ __launch_bounds__(256) void transpose_h_kernel(
    const float* __restrict__ V, __half* __restrict__ VTh, int R, int Ccols)
{
    __shared__ float tbuf[32][33];
    int c0 = blockIdx.x * 32, r0 = blockIdx.y * 32;
    int x = threadIdx.x, y = threadIdx.y;
#pragma unroll
    for (int j = 0; j < 32; j += 8)
        tbuf[y + j][x] = V[(size_t)(r0 + y + j) * Ccols + c0 + x];
    __syncthreads();
    int k = x & 15;
    int px = (x & ~15) + 4 * ((k & 7) >> 1) + (k & 1) + 2 * (k >> 3);
#pragma unroll
    for (int j = 0; j < 32; j += 8)
        VTh[(size_t)(c0 + y + j) * R + r0 + px] = __float2half_rn(tbuf[x][y + j]);
}

__global__ __launch_bounds__(256) void sum4_h_kernel(
    const uint4* __restrict__ p, float4* __restrict__ out, int n8, size_t stride8)
{
    int i = blockIdx.x * 256 + threadIdx.x;
    if (i >= n8) return;
    float r[8];
#pragma unroll
    for (int j = 0; j < 8; j++) r[j] = 0.f;
#pragma unroll
    for (int z = 0; z < 4; z++) {
        uint4 u = p[i + z * stride8];
        uint32_t w[4] = {u.x, u.y, u.z, u.w};
#pragma unroll
        for (int j = 0; j < 4; j++) {
            float2 xy = __half22float2(*reinterpret_cast<__half2*>(&w[j]));
            r[2 * j]     += xy.x;
            r[2 * j + 1] += xy.y;
        }
    }
    out[2 * i]     = make_float4(r[0], r[1], r[2], r[3]);
    out[2 * i + 1] = make_float4(r[4], r[5], r[6], r[7]);
}

// ---------------------------------------------------------------------------
extern "C" void kernel_launch(void* const* d_in, const int* in_sizes, int n_in,
                              void* d_out, int out_size)
{
    const float* q = (const float*)d_in[0];
    const float* k = (const float*)d_in[1];
    const float* v = (const float*)d_in[2];
    float* out = (float*)d_out;

    float *SQ, *RS;
    __half *Gh, *VTh, *QTh, *KTh, *P;
    cudaGetSymbolAddress((void**)&Gh,  g_Gh);
    cudaGetSymbolAddress((void**)&VTh, g_VTh);
    cudaGetSymbolAddress((void**)&QTh, g_QTh);
    cudaGetSymbolAddress((void**)&KTh, g_KTh);
    cudaGetSymbolAddress((void**)&P,   g_P);
    cudaGetSymbolAddress((void**)&SQ,  g_SQ);
    cudaGetSymbolAddress((void**)&RS,  g_RS);

    static cudaStream_t s2 = nullptr;
    static cudaEvent_t evFork = nullptr, evJoin = nullptr;
    static bool init_done = false;
    if (!init_done) {
        cudaFuncSetAttribute((const void*)gemm_fp16<true>,
                             cudaFuncAttributeMaxDynamicSharedMemorySize, SMEMH_BYTES);
        cudaFuncSetAttribute((const void*)gemm_fp16<false>,
                             cudaFuncAttributeMaxDynamicSharedMemorySize, SMEMH_BYTES);
        cudaStreamCreateWithFlags(&s2, cudaStreamNonBlocking);
        cudaEventCreateWithFlags(&evFork, cudaEventDisableTiming);
        cudaEventCreateWithFlags(&evJoin, cudaEventDisableTiming);
        init_done = true;
    }

    const int M = 8192, NBANK = 8192, D = 1024;
    const int ngroups = (M * D) / 16;
    const int KCHUNK = 2048;

    // fork: v-transpose on side stream
    cudaEventRecord(evFork, 0);
    cudaStreamWaitEvent(s2, evFork, 0);
    transpose_h_kernel<<<dim3(D / 32, NBANK / 32), dim3(32, 8), 0, s2>>>(v, VTh, NBANK, D);
    cudaEventRecord(evJoin, s2);

    // q + k staging
    stage_h2_kernel<<<dim3((ngroups + 255) / 256, 2), 256>>>(
        (const float4*)q, QTh, (const float4*)k, KTh, ngroups);

    // S = q @ k^T -> fp16, P2 cols, fused row-sumsq
    gemm_fp16<true><<<dim3(NBANK / BN, M / BM, 1), 256, SMEMH_BYTES>>>(
        QTh, KTh, Gh, SQ, M, NBANK, D, D, D);

    // row scales, then in-place gelu
    row_scale_kernel<<<M / 8, 256>>>(SQ, RS, NBANK);
    norm_gelu_inplace_kernel<<<M, 256>>>(Gh, RS, NBANK);

    // join: VT ready
    cudaStreamWaitEvent(0, evJoin, 0);

    // out partials (fp16) = G @ vT^T, split-K x4
    gemm_fp16<false><<<dim3(D / BN, M / BM, 4), 256, SMEMH_BYTES>>>(
        Gh, VTh, P, nullptr, M, D, KCHUNK, NBANK, NBANK);

    const int n8 = (M * D) / 8;
    sum4_h_kernel<<<(n8 + 255) / 256, 256>>>((const uint4*)P, (float4*)out, n8,
                                             (size_t)M * D / 8);
}